// round 3
// baseline (speedup 1.0000x reference)
#include <cuda_runtime.h>

// Problem constants
#define CC    768        // channels
#define NO    197        // tokens per frame (N_origin)
#define FRn   8          // FRAMES
#define BBn   8          // batch after frame-fold (64/8)
#define NNt   1576       // FRn*NO
#define HHn   12         // heads
#define HDn   64         // head dim
#define MMn   204        // gathered tokens (8 cls + 196)
#define ROWSn 12608      // BBn*NNt (= 64*197)
#define GRn   1632       // BBn*MMn

#define SMEM_ATTN (2 * MMn * HDn * 4)   // K + V tiles in fp32 = 104448 B

// Scratch (device globals; no allocation allowed)
__device__ float g_Q[ROWSn * CC];                 // Q projection, token-major
__device__ float g_K[BBn * HHn * MMn * HDn];      // gathered K, [b][h][m][d]
__device__ float g_V[BBn * HHn * MMn * HDn];      // gathered V, [b][h][m][d]
__device__ float g_O[ROWSn * CC];                 // attention output, token-major

// token index of gathered column m (matches _build_indices_mask)
__device__ __forceinline__ int token_of(int m) {
    if (m < 8) return m * NO;            // cls tokens
    int r = m - 8;
    int f, j;
    if (r < 100) { f = r / 25; j = r - f * 25; }     // frames 0..3, len 25
    else { r -= 100; f = 4 + r / 24; j = r % 24; }   // frames 4..7, len 24
    return f * NO + 1 + f + 8 * j;
}

// ---------------------------------------------------------------------------
// GEMM 1: Q = X @ Wq^T   (12608 x 768, K=768). Both operands K-contiguous (NT).
// 128x128 tile, BK=16, 256 threads, 8x8 microtile.
// ---------------------------------------------------------------------------
__global__ __launch_bounds__(256) void gemm_q_kernel(
    const float* __restrict__ A, const float* __restrict__ W)
{
    __shared__ float As[16][132];
    __shared__ float Bs[16][132];
    const int t = threadIdx.x;
    const int row0 = blockIdx.x * 128;
    const int col0 = blockIdx.y * 128;
    const int lr = t >> 2;          // 0..63
    const int lk = (t & 3) << 2;    // 0,4,8,12
    const int ty = t >> 4, tx = t & 15;

    float acc[8][8];
#pragma unroll
    for (int i = 0; i < 8; i++)
#pragma unroll
        for (int j = 0; j < 8; j++) acc[i][j] = 0.f;

    const int r0 = row0 + lr, r1 = row0 + lr + 64;
    const int c0 = col0 + lr, c1 = col0 + lr + 64;   // always < 768 by grid

    for (int k0 = 0; k0 < CC; k0 += 16) {
        float4 va0 = (r0 < ROWSn) ? *(const float4*)(A + (size_t)r0 * CC + k0 + lk)
                                  : make_float4(0.f, 0.f, 0.f, 0.f);
        float4 va1 = (r1 < ROWSn) ? *(const float4*)(A + (size_t)r1 * CC + k0 + lk)
                                  : make_float4(0.f, 0.f, 0.f, 0.f);
        float4 vb0 = *(const float4*)(W + (size_t)c0 * CC + k0 + lk);
        float4 vb1 = *(const float4*)(W + (size_t)c1 * CC + k0 + lk);

        As[lk + 0][lr] = va0.x; As[lk + 1][lr] = va0.y;
        As[lk + 2][lr] = va0.z; As[lk + 3][lr] = va0.w;
        As[lk + 0][lr + 64] = va1.x; As[lk + 1][lr + 64] = va1.y;
        As[lk + 2][lr + 64] = va1.z; As[lk + 3][lr + 64] = va1.w;
        Bs[lk + 0][lr] = vb0.x; Bs[lk + 1][lr] = vb0.y;
        Bs[lk + 2][lr] = vb0.z; Bs[lk + 3][lr] = vb0.w;
        Bs[lk + 0][lr + 64] = vb1.x; Bs[lk + 1][lr + 64] = vb1.y;
        Bs[lk + 2][lr + 64] = vb1.z; Bs[lk + 3][lr + 64] = vb1.w;
        __syncthreads();

#pragma unroll
        for (int kk = 0; kk < 16; kk++) {
            float a[8], b[8];
#pragma unroll
            for (int i = 0; i < 8; i++) a[i] = As[kk][ty * 8 + i];
#pragma unroll
            for (int j = 0; j < 8; j++) b[j] = Bs[kk][tx * 8 + j];
#pragma unroll
            for (int i = 0; i < 8; i++)
#pragma unroll
                for (int j = 0; j < 8; j++) acc[i][j] += a[i] * b[j];
        }
        __syncthreads();
    }

#pragma unroll
    for (int i = 0; i < 8; i++) {
        int r = row0 + ty * 8 + i;
        if (r < ROWSn) {
            float* dst = g_Q + (size_t)r * CC + col0 + tx * 8;
            *(float4*)(dst)     = make_float4(acc[i][0], acc[i][1], acc[i][2], acc[i][3]);
            *(float4*)(dst + 4) = make_float4(acc[i][4], acc[i][5], acc[i][6], acc[i][7]);
        }
    }
}

// ---------------------------------------------------------------------------
// GEMM 2: gathered K/V projection. Rows = 1632 gathered tokens, cols = 1536
// (K then V). Scatters into g_K / g_V in [b][h][m][d] layout.
// ---------------------------------------------------------------------------
__global__ __launch_bounds__(256) void gemm_kv_kernel(
    const float* __restrict__ A, const float* __restrict__ W)
{
    __shared__ float As[16][132];
    __shared__ float Bs[16][132];
    const int t = threadIdx.x;
    const int row0 = blockIdx.x * 128;
    const int col0 = blockIdx.y * 128;
    const int lr = t >> 2;
    const int lk = (t & 3) << 2;
    const int ty = t >> 4, tx = t & 15;

    float acc[8][8];
#pragma unroll
    for (int i = 0; i < 8; i++)
#pragma unroll
        for (int j = 0; j < 8; j++) acc[i][j] = 0.f;

    // precompute gathered source rows for the two A rows this thread loads
    int src[2];
#pragma unroll
    for (int i = 0; i < 2; i++) {
        int gr = row0 + lr + i * 64;
        if (gr < GRn) {
            int b = gr / MMn;
            int m = gr - b * MMn;
            src[i] = b * NNt + token_of(m);
        } else src[i] = -1;
    }
    const int c0 = col0 + lr, c1 = col0 + lr + 64;  // always < 1536 by grid

    for (int k0 = 0; k0 < CC; k0 += 16) {
        float4 va0 = (src[0] >= 0) ? *(const float4*)(A + (size_t)src[0] * CC + k0 + lk)
                                   : make_float4(0.f, 0.f, 0.f, 0.f);
        float4 va1 = (src[1] >= 0) ? *(const float4*)(A + (size_t)src[1] * CC + k0 + lk)
                                   : make_float4(0.f, 0.f, 0.f, 0.f);
        float4 vb0 = *(const float4*)(W + (size_t)c0 * CC + k0 + lk);
        float4 vb1 = *(const float4*)(W + (size_t)c1 * CC + k0 + lk);

        As[lk + 0][lr] = va0.x; As[lk + 1][lr] = va0.y;
        As[lk + 2][lr] = va0.z; As[lk + 3][lr] = va0.w;
        As[lk + 0][lr + 64] = va1.x; As[lk + 1][lr + 64] = va1.y;
        As[lk + 2][lr + 64] = va1.z; As[lk + 3][lr + 64] = va1.w;
        Bs[lk + 0][lr] = vb0.x; Bs[lk + 1][lr] = vb0.y;
        Bs[lk + 2][lr] = vb0.z; Bs[lk + 3][lr] = vb0.w;
        Bs[lk + 0][lr + 64] = vb1.x; Bs[lk + 1][lr + 64] = vb1.y;
        Bs[lk + 2][lr + 64] = vb1.z; Bs[lk + 3][lr + 64] = vb1.w;
        __syncthreads();

#pragma unroll
        for (int kk = 0; kk < 16; kk++) {
            float a[8], b[8];
#pragma unroll
            for (int i = 0; i < 8; i++) a[i] = As[kk][ty * 8 + i];
#pragma unroll
            for (int j = 0; j < 8; j++) b[j] = Bs[kk][tx * 8 + j];
#pragma unroll
            for (int i = 0; i < 8; i++)
#pragma unroll
                for (int j = 0; j < 8; j++) acc[i][j] += a[i] * b[j];
        }
        __syncthreads();
    }

#pragma unroll
    for (int i = 0; i < 8; i++) {
        int gr = row0 + ty * 8 + i;
        if (gr >= GRn) continue;
        int b = gr / MMn;
        int m = gr - b * MMn;
#pragma unroll
        for (int j = 0; j < 8; j++) {
            int c = col0 + tx * 8 + j;
            if (c < 768) {
                int h = c >> 6, d = c & 63;
                g_K[(((size_t)b * HHn + h) * MMn + m) * HDn + d] = acc[i][j];
            } else {
                int c2 = c - 768;
                int h = c2 >> 6, d = c2 & 63;
                g_V[(((size_t)b * HHn + h) * MMn + m) * HDn + d] = acc[i][j];
            }
        }
    }
}

// ---------------------------------------------------------------------------
// Attention: one thread per query row, K/V tile (204x64 each) in SMEM,
// online softmax, logits multiplied by mask (1.0 / 0.8) then softmax.
// ---------------------------------------------------------------------------
__global__ __launch_bounds__(256) void attn_kernel()
{
    extern __shared__ float sm[];
    float* Ks = sm;
    float* Vs = sm + MMn * HDn;
    const int bh = blockIdx.x;                   // 0..95 = b*12+h
    const float* Kg = g_K + (size_t)bh * MMn * HDn;
    const float* Vg = g_V + (size_t)bh * MMn * HDn;

    for (int i = threadIdx.x; i < MMn * HDn / 4; i += 256) {
        ((float4*)Ks)[i] = ((const float4*)Kg)[i];
        ((float4*)Vs)[i] = ((const float4*)Vg)[i];
    }
    __syncthreads();

    const int n = blockIdx.y * 256 + threadIdx.x;
    if (n >= NNt) return;
    const int b = bh / HHn, h = bh % HHn;
    const int frame = n / NO;
    const int cstart = (frame < 4) ? (8 + 25 * frame) : (108 + 24 * (frame - 4));
    const int cend = cstart + ((frame < 4) ? 25 : 24);

    float q[64], acc[64];
    {
        const float4* q4 = (const float4*)(g_Q + (size_t)(b * NNt + n) * CC + h * HDn);
#pragma unroll
        for (int i = 0; i < 16; i++) ((float4*)q)[i] = q4[i];
    }
#pragma unroll
    for (int d = 0; d < 64; d++) acc[d] = 0.f;

    float mx = -1e30f, den = 0.f;
    for (int m = 0; m < MMn; m++) {
        const float4* k4 = (const float4*)(Ks + m * HDn);
        float s = 0.f;
#pragma unroll
        for (int i = 0; i < 16; i++) {
            float4 kv = k4[i];
            s += q[4 * i] * kv.x + q[4 * i + 1] * kv.y
               + q[4 * i + 2] * kv.z + q[4 * i + 3] * kv.w;
        }
        // (q.k * scale) * mask ; scale = 0.125, mask in {1.0, 0.8}
        float mult = (m < 8 || (m >= cstart && m < cend)) ? 0.125f : 0.1f;
        s *= mult;

        const float4* v4 = (const float4*)(Vs + m * HDn);
        if (s <= mx) {
            float p = __expf(s - mx);
            den += p;
#pragma unroll
            for (int i = 0; i < 16; i++) {
                float4 vv = v4[i];
                acc[4 * i]     += p * vv.x;
                acc[4 * i + 1] += p * vv.y;
                acc[4 * i + 2] += p * vv.z;
                acc[4 * i + 3] += p * vv.w;
            }
        } else {
            float cr = __expf(mx - s);
            den = den * cr + 1.f;
#pragma unroll
            for (int i = 0; i < 16; i++) {
                float4 vv = v4[i];
                acc[4 * i]     = acc[4 * i]     * cr + vv.x;
                acc[4 * i + 1] = acc[4 * i + 1] * cr + vv.y;
                acc[4 * i + 2] = acc[4 * i + 2] * cr + vv.z;
                acc[4 * i + 3] = acc[4 * i + 3] * cr + vv.w;
            }
            mx = s;
        }
    }

    const float inv = 1.f / den;
    float* o = g_O + (size_t)(b * NNt + n) * CC + h * HDn;
#pragma unroll
    for (int i = 0; i < 16; i++) {
        ((float4*)o)[i] = make_float4(acc[4 * i] * inv, acc[4 * i + 1] * inv,
                                      acc[4 * i + 2] * inv, acc[4 * i + 3] * inv);
    }
}

// ---------------------------------------------------------------------------
// GEMM 3: out = g_O @ proj_w^T + proj_b   (12608 x 768, K=768)
// ---------------------------------------------------------------------------
__global__ __launch_bounds__(256) void gemm_proj_kernel(
    const float* __restrict__ W, const float* __restrict__ bias,
    float* __restrict__ Cout)
{
    __shared__ float As[16][132];
    __shared__ float Bs[16][132];
    const int t = threadIdx.x;
    const int row0 = blockIdx.x * 128;
    const int col0 = blockIdx.y * 128;
    const int lr = t >> 2;
    const int lk = (t & 3) << 2;
    const int ty = t >> 4, tx = t & 15;
    const float* A = g_O;

    float acc[8][8];
#pragma unroll
    for (int i = 0; i < 8; i++)
#pragma unroll
        for (int j = 0; j < 8; j++) acc[i][j] = 0.f;

    const int r0 = row0 + lr, r1 = row0 + lr + 64;
    const int c0 = col0 + lr, c1 = col0 + lr + 64;

    for (int k0 = 0; k0 < CC; k0 += 16) {
        float4 va0 = (r0 < ROWSn) ? *(const float4*)(A + (size_t)r0 * CC + k0 + lk)
                                  : make_float4(0.f, 0.f, 0.f, 0.f);
        float4 va1 = (r1 < ROWSn) ? *(const float4*)(A + (size_t)r1 * CC + k0 + lk)
                                  : make_float4(0.f, 0.f, 0.f, 0.f);
        float4 vb0 = *(const float4*)(W + (size_t)c0 * CC + k0 + lk);
        float4 vb1 = *(const float4*)(W + (size_t)c1 * CC + k0 + lk);

        As[lk + 0][lr] = va0.x; As[lk + 1][lr] = va0.y;
        As[lk + 2][lr] = va0.z; As[lk + 3][lr] = va0.w;
        As[lk + 0][lr + 64] = va1.x; As[lk + 1][lr + 64] = va1.y;
        As[lk + 2][lr + 64] = va1.z; As[lk + 3][lr + 64] = va1.w;
        Bs[lk + 0][lr] = vb0.x; Bs[lk + 1][lr] = vb0.y;
        Bs[lk + 2][lr] = vb0.z; Bs[lk + 3][lr] = vb0.w;
        Bs[lk + 0][lr + 64] = vb1.x; Bs[lk + 1][lr + 64] = vb1.y;
        Bs[lk + 2][lr + 64] = vb1.z; Bs[lk + 3][lr + 64] = vb1.w;
        __syncthreads();

#pragma unroll
        for (int kk = 0; kk < 16; kk++) {
            float a[8], b[8];
#pragma unroll
            for (int i = 0; i < 8; i++) a[i] = As[kk][ty * 8 + i];
#pragma unroll
            for (int j = 0; j < 8; j++) b[j] = Bs[kk][tx * 8 + j];
#pragma unroll
            for (int i = 0; i < 8; i++)
#pragma unroll
                for (int j = 0; j < 8; j++) acc[i][j] += a[i] * b[j];
        }
        __syncthreads();
    }

    float bv[8];
#pragma unroll
    for (int j = 0; j < 8; j++) bv[j] = bias[col0 + tx * 8 + j];

#pragma unroll
    for (int i = 0; i < 8; i++) {
        int r = row0 + ty * 8 + i;
        if (r < ROWSn) {
            float* dst = Cout + (size_t)r * CC + col0 + tx * 8;
            *(float4*)(dst)     = make_float4(acc[i][0] + bv[0], acc[i][1] + bv[1],
                                              acc[i][2] + bv[2], acc[i][3] + bv[3]);
            *(float4*)(dst + 4) = make_float4(acc[i][4] + bv[4], acc[i][5] + bv[5],
                                              acc[i][6] + bv[6], acc[i][7] + bv[7]);
        }
    }
}

// ---------------------------------------------------------------------------
extern "C" void kernel_launch(void* const* d_in, const int* in_sizes, int n_in,
                              void* d_out, int out_size)
{
    const float* x      = (const float*)d_in[0];
    const float* qkv_w  = (const float*)d_in[1];
    const float* proj_w = (const float*)d_in[2];
    const float* proj_b = (const float*)d_in[3];
    float* out = (float*)d_out;

    cudaFuncSetAttribute(attn_kernel,
                         cudaFuncAttributeMaxDynamicSharedMemorySize, SMEM_ATTN);

    dim3 blk(256);
    // Q projection: 12608 x 768
    gemm_q_kernel<<<dim3(99, 6), blk>>>(x, qkv_w);
    // gathered K/V projection: 1632 x 1536 (uses qkv_w rows 768..2303)
    gemm_kv_kernel<<<dim3(13, 12), blk>>>(x, qkv_w + 768 * CC);
    // attention: 96 (b,h) blocks x 7 query tiles
    attn_kernel<<<dim3(96, 7), blk, SMEM_ATTN>>>();
    // output projection + bias: 12608 x 768
    gemm_proj_kernel<<<dim3(99, 6), blk>>>(proj_w, proj_b, out);
}